// round 11
// baseline (speedup 1.0000x reference)
#include <cuda_runtime.h>

// InfoEnlargeEmbedding: out[b,l,:] = concat(x[b,l,:], x[b,idxs[b,0],:], x[b,idxs[b,1],:])
// B=64, L=1024, D=256, K=2.
// R11: split into two stream-pure kernels.
//   K1: strided memcpy of the copy region (reads x, writes 67MB).
//   K2: pure broadcast-write of the gather region (134MB stores, reg-sourced).
// Tests whether the ~5.2TB/s cap is an artifact of mixing read service with
// write drain in every SM simultaneously.

static constexpr int B = 64;
static constexpr int L = 1024;
static constexpr int D4 = 64;               // float4 per source row
static constexpr int K = 2;
static constexpr int OUT4 = D4 * (1 + K);   // 192 float4 per output row

// ---- K1: copy region. Linear over B*L*D4 float4, unroll 8 for MLP. ----
static constexpr int CP_TOTAL = B * L * D4; // 4,194,304 float4
static constexpr int CP_T = 256;
static constexpr int CP_U = 8;
static constexpr int CP_GRID = CP_TOTAL / (CP_T * CP_U);  // 2048

__global__ void __launch_bounds__(CP_T)
copy_kernel(const float4* __restrict__ x, float4* __restrict__ out) {
    const int base = (blockIdx.x * CP_T * CP_U) + threadIdx.x;
    float4 v[CP_U];
    #pragma unroll
    for (int u = 0; u < CP_U; u++)
        v[u] = x[base + u * CP_T];
    #pragma unroll
    for (int u = 0; u < CP_U; u++) {
        const int i = base + u * CP_T;
        const int bl = i >> 6, c = i & (D4 - 1);
        out[(size_t)bl * OUT4 + c] = v[u];
    }
}

// ---- K2: gather region. 128 threads own one column each; 32 rows/block. ----
static constexpr int G_T = 128;             // one thread per gather float4 column
static constexpr int G_ROWS = 32;           // rows per block
static constexpr int G_GRID = (B * L) / G_ROWS;  // 2048

__global__ void __launch_bounds__(G_T)
gather_kernel(const float4* __restrict__ x, const int* __restrict__ idxs,
              float4* __restrict__ out) {
    const int row0 = blockIdx.x * G_ROWS;   // all rows share b (G_ROWS | L)
    const int b    = row0 >> 10;
    const int g    = threadIdx.x;           // 0..127
    const int k    = g >> 6;
    const int dd   = g & (D4 - 1);
    const int li   = __ldg(idxs + b * K + k);
    const float4 v = __ldg(x + ((size_t)b * L + li) * D4 + dd);

    float4* o = out + (size_t)row0 * OUT4 + D4 + g;
    #pragma unroll
    for (int u = 0; u < G_ROWS; u++)
        o[(size_t)u * OUT4] = v;
}

extern "C" void kernel_launch(void* const* d_in, const int* in_sizes, int n_in,
                              void* d_out, int out_size) {
    const float4* x  = (const float4*)d_in[0];
    const int* idxs  = (const int*)d_in[1];
    float4* out      = (float4*)d_out;

    gather_kernel<<<G_GRID, G_T>>>(x, idxs, out);
    copy_kernel<<<CP_GRID, CP_T>>>(x, out);
}

// round 12
// speedup vs baseline: 1.0957x; 1.0957x over previous
#include <cuda_runtime.h>

// InfoEnlargeEmbedding: out[b,l,:] = concat(x[b,l,:], x[b,idxs[b,0],:], x[b,idxs[b,1],:])
// B=64, L=1024, D=256, K=2.
// R12: block-specialized single launch. 2048 copy blocks (K1's 7.3TB/s linear
// body) + 4096 gather blocks (16 rows, load-once/store-8 per thread),
// interleaved (g,g,c) so read and write streams coexist chip-wide while each
// block stays internally homogeneous.

static constexpr int B = 64;
static constexpr int L = 1024;
static constexpr int D4 = 64;               // float4 per source row
static constexpr int K = 2;
static constexpr int OUT4 = D4 * (1 + K);   // 192 float4 per output row
static constexpr int T = 256;

// copy section
static constexpr int CP_U = 8;
static constexpr int CP_BLOCKS = (B * L * D4) / (T * CP_U);  // 2048

// gather section
static constexpr int G_ROWS = 16;                            // rows per gather block
static constexpr int G_BLOCKS = (B * L) / G_ROWS;            // 4096
static constexpr int GRT = G_ROWS / 2;                       // 8 stores per thread

static constexpr int GRID = CP_BLOCKS + G_BLOCKS;            // 6144

__global__ void __launch_bounds__(T)
info_enlarge_kernel(const float4* __restrict__ x,
                    const int* __restrict__ idxs,
                    float4* __restrict__ out) {
    const int i = blockIdx.x;
    const int tri = i / 3, rem = i - tri * 3;
    const int t = threadIdx.x;

    if (rem < 2) {
        // ---- gather block: tile of 16 rows, broadcast writes ----
        const int tile = tri * 2 + rem;         // 0..4095
        const int row0 = tile * G_ROWS;         // same b across tile
        const int b    = row0 >> 10;
        const int g    = t & 127;               // gather column 0..127
        const int h    = t >> 7;                // row half
        const int k    = g >> 6;
        const int dd   = g & (D4 - 1);
        const int li   = __ldg(idxs + b * K + k);
        const float4 v = __ldg(x + ((size_t)b * L + li) * D4 + dd);

        float4* o = out + (size_t)(row0 + h * GRT) * OUT4 + D4 + g;
        #pragma unroll
        for (int u = 0; u < GRT; u++)
            o[(size_t)u * OUT4] = v;
    } else {
        // ---- copy block: linear 8-way unrolled strided memcpy ----
        const int ci   = tri;                   // 0..2047
        const int base = ci * (T * CP_U) + t;
        float4 v[CP_U];
        #pragma unroll
        for (int u = 0; u < CP_U; u++)
            v[u] = x[base + u * T];
        #pragma unroll
        for (int u = 0; u < CP_U; u++) {
            const int idx = base + u * T;
            const int bl = idx >> 6, c = idx & (D4 - 1);
            out[(size_t)bl * OUT4 + c] = v[u];
        }
    }
}

extern "C" void kernel_launch(void* const* d_in, const int* in_sizes, int n_in,
                              void* d_out, int out_size) {
    const float4* x  = (const float4*)d_in[0];
    const int* idxs  = (const int*)d_in[1];
    float4* out      = (float4*)d_out;

    info_enlarge_kernel<<<GRID, T>>>(x, idxs, out);
}